// round 9
// baseline (speedup 1.0000x reference)
#include <cuda_runtime.h>
#include <cuda_fp16.h>
#include <stdint.h>
#include <math.h>

#define NN 200000
#define NE 6400000
#define NG 64
#define NB_SCAN 782   // ceil(NN/256); all blocks resident

// ---- device scratch (static, no runtime allocation) ----
__device__ int    g_count[NN];        // in-degree
__device__ int    g_cursor[NN];       // scatter cursor
__device__ int    g_off[NN];          // CSR offsets (exclusive scan)
__device__ int    g_bsum[1024];       // scan block totals
__device__ int    g_sync[4];          // global sync counters
__device__ uint4  g_sorted[NE];       // {src, ef01(half2), ef23(half2), 0} sorted by dst
__device__ __half g_nfh[NN * 8];      // node_feat as half, padded to 8/row (16B)
__device__ __half g_h1h[NN * 32];     // layer-1 output (fp16, 12.8MB)
__device__ float  g_pooled[NG * 32];

// ---------------- setup: zero scratch + pad/convert node features ----------------
__global__ void setup_kernel(const float* __restrict__ node_feat) {
    int i = blockIdx.x * blockDim.x + threadIdx.x;
    if (i < NN * 8) {
        int n = i >> 3, k = i & 7;
        g_nfh[i] = __float2half_rn((k < 7) ? node_feat[n * 7 + k] : 0.0f);
    }
    if (i < NN) { g_count[i] = 0; g_cursor[i] = 0; }
    if (i < NG * 32) g_pooled[i] = 0.0f;
    if (i < 4) g_sync[i] = 0;
}

__device__ __forceinline__ unsigned int pack_h2(float a, float b) {
    __half2 h = __floats2half2_rn(a, b);
    return *(unsigned int*)&h;
}

__device__ __forceinline__ void gsync(int idx) {
    __syncthreads();
    __threadfence();
    if (threadIdx.x == 0) {
        atomicAdd(&g_sync[idx], 1);
        while (atomicAdd(&g_sync[idx], 0) < NB_SCAN) { }
    }
    __syncthreads();
}

// ---------------- persistent sort: hist -> scan -> scatter ----------------
__global__ void sort_kernel(const int4* __restrict__ src4,
                            const int4* __restrict__ dst4,
                            const float4* __restrict__ ef4) {
    __shared__ int s[256];
    int t = threadIdx.x;
    int b = blockIdx.x;
    int i = b * 256 + t;
    const int nquads = NE / 4;

    // --- phase 0: histogram of dst ---
    for (int q = b * 256 + t; q < nquads; q += NB_SCAN * 256) {
        int4 d = dst4[q];
        atomicAdd(&g_count[d.x], 1);
        atomicAdd(&g_count[d.y], 1);
        atomicAdd(&g_count[d.z], 1);
        atomicAdd(&g_count[d.w], 1);
    }
    gsync(0);

    // --- phase 1: block-local inclusive scan of degrees ---
    int v = (i < NN) ? g_count[i] : 0;
    s[t] = v;
    __syncthreads();
    for (int off = 1; off < 256; off <<= 1) {
        int add = (t >= off) ? s[t - off] : 0;
        __syncthreads();
        s[t] += add;
        __syncthreads();
    }
    int local_excl = s[t] - v;
    if (t == 255) {
        g_bsum[b] = s[255];
        __threadfence();
        atomicAdd(&g_sync[1], 1);
    }
    if (t == 0) { while (atomicAdd(&g_sync[1], 0) < NB_SCAN) { } }
    __syncthreads();

    // --- phase 2: block prefix from published totals ---
    int pre = 0;
    for (int k = t; k < b; k += 256) pre += g_bsum[k];
    s[t] = pre;
    __syncthreads();
    for (int o = 128; o; o >>= 1) {
        if (t < o) s[t] += s[t + o];
        __syncthreads();
    }
    if (i < NN) g_off[i] = s[0] + local_excl;

    gsync(2);

    // --- phase 3: grid-stride scatter of packed {src, fp16 edge_feat} ---
    for (int q = b * 256 + t; q < nquads; q += NB_SCAN * 256) {
        int4 sv = src4[q];
        int4 dv = dst4[q];
        float4 e0 = ef4[q * 4 + 0];
        float4 e1 = ef4[q * 4 + 1];
        float4 e2 = ef4[q * 4 + 2];
        float4 e3 = ef4[q * 4 + 3];
        uint4 w;
        w.w = 0u;

        int p0 = g_off[dv.x] + atomicAdd(&g_cursor[dv.x], 1);
        w.x = (unsigned int)sv.x; w.y = pack_h2(e0.x, e0.y); w.z = pack_h2(e0.z, e0.w);
        g_sorted[p0] = w;
        int p1 = g_off[dv.y] + atomicAdd(&g_cursor[dv.y], 1);
        w.x = (unsigned int)sv.y; w.y = pack_h2(e1.x, e1.y); w.z = pack_h2(e1.z, e1.w);
        g_sorted[p1] = w;
        int p2 = g_off[dv.z] + atomicAdd(&g_cursor[dv.z], 1);
        w.x = (unsigned int)sv.z; w.y = pack_h2(e2.x, e2.y); w.z = pack_h2(e2.z, e2.w);
        g_sorted[p2] = w;
        int p3 = g_off[dv.w] + atomicAdd(&g_cursor[dv.w], 1);
        w.x = (unsigned int)sv.w; w.y = pack_h2(e3.x, e3.y); w.z = pack_h2(e3.z, e3.w);
        g_sorted[p3] = w;
    }
}

// ---------------- layer 1: sequential edge stream + one fp16 nf gather ----------------
__global__ void node1_kernel(const float* __restrict__ W1a, const float* __restrict__ b1a,
                             const float* __restrict__ W1b, const float* __restrict__ b1b) {
    __shared__ float sW1a[11 * 32];
    __shared__ float sW1b[32 * 32];
    __shared__ float sb1a[32];
    __shared__ float sb1b[32];
    int tid = threadIdx.x;
    for (int k = tid; k < 11 * 32; k += blockDim.x) sW1a[k] = W1a[k];
    for (int k = tid; k < 32 * 32; k += blockDim.x) sW1b[k] = W1b[k];
    if (tid < 32) { sb1a[tid] = b1a[tid]; sb1b[tid] = b1b[tid]; }
    __syncthreads();

    int warp = tid >> 5;
    int lane = tid & 31;
    int n = blockIdx.x * (blockDim.x >> 5) + warp;
    if (n >= NN) return;

    int start = g_off[n];
    int deg   = g_count[n];

    float acc[11];
#pragma unroll
    for (int k = 0; k < 11; k++) acc[k] = 0.0f;

    const uint4* nfq = (const uint4*)g_nfh;
    for (int j = lane; j < deg; j += 32) {
        uint4 p = __ldg(&g_sorted[start + j]);   // coalesced 16B stream
        __half2 h01 = *(__half2*)&p.y;
        __half2 h23 = *(__half2*)&p.z;
        float2 e01 = __half22float2(h01);
        float2 e23 = __half22float2(h23);
        acc[0] += e01.x; acc[1] += e01.y; acc[2] += e23.x; acc[3] += e23.y;
        uint4 nf = __ldg(&nfq[p.x]);             // ONE 16B gather (L2-resident)
        __half2 n0 = *(__half2*)&nf.x;
        __half2 n1 = *(__half2*)&nf.y;
        __half2 n2 = *(__half2*)&nf.z;
        __half2 n3 = *(__half2*)&nf.w;
        float2 f0 = __half22float2(n0);
        float2 f1 = __half22float2(n1);
        float2 f2 = __half22float2(n2);
        float2 f3 = __half22float2(n3);
        acc[4] += f0.x; acc[5] += f0.y;
        acc[6] += f1.x; acc[7] += f1.y;
        acc[8] += f2.x; acc[9] += f2.y;
        acc[10] += f3.x;
    }

#pragma unroll
    for (int off = 16; off; off >>= 1) {
#pragma unroll
        for (int k = 0; k < 11; k++)
            acc[k] += __shfl_xor_sync(0xffffffffu, acc[k], off);
    }

    float invd = 1.0f / fmaxf((float)deg, 1.0f);

    float y = sb1a[lane];
#pragma unroll
    for (int k = 0; k < 11; k++)
        y = fmaf(acc[k] * invd, sW1a[k * 32 + lane], y);
    y = fmaxf(y, 0.0f);

    float z = sb1b[lane];
#pragma unroll
    for (int k = 0; k < 32; k++) {
        float yk = __shfl_sync(0xffffffffu, y, k);
        z = fmaf(yk, sW1b[k * 32 + lane], z);
    }
    z = fmaxf(z, 0.0f);

    g_h1h[n * 32 + lane] = __float2half_rn(z);
}

// ---------------- layer 2: half2 dual-edge gather (16-edge ILP) + MLP + pool ----------------
__global__ void node2_kernel(const float* __restrict__ W2a, const float* __restrict__ b2a,
                             const float* __restrict__ W2b, const float* __restrict__ b2b,
                             const int* __restrict__ graph_ids) {
    __shared__ float sW2a[32 * 32];
    __shared__ float sW2b[32 * 32];
    __shared__ float sb2a[32];
    __shared__ float sb2b[32];
    int tid = threadIdx.x;
    for (int k = tid; k < 32 * 32; k += blockDim.x) { sW2a[k] = W2a[k]; sW2b[k] = W2b[k]; }
    if (tid < 32) { sb2a[tid] = b2a[tid]; sb2b[tid] = b2b[tid]; }
    __syncthreads();

    int warp = tid >> 5;
    int lane = tid & 31;
    int n = blockIdx.x * (blockDim.x >> 5) + warp;
    if (n >= NN) return;

    int start = g_off[n];
    int deg   = g_count[n];

    int half = lane >> 4;     // 0: even edges, 1: odd edges
    int fl   = lane & 15;     // feature-pair index (features 2*fl, 2*fl+1)
    const __half2* h1p = (const __half2*)g_h1h;

    float2 a0 = make_float2(0.f, 0.f);
    float2 a1 = make_float2(0.f, 0.f);
    float2 a2 = make_float2(0.f, 0.f);
    float2 a3 = make_float2(0.f, 0.f);

    int j = 0;
    for (; j + 16 <= deg; j += 16) {
        int idx = 0;
        if (lane < 16) idx = (int)g_sorted[start + j + lane].x;
        int r0 = __shfl_sync(0xffffffffu, idx,  0 + half);
        int r1 = __shfl_sync(0xffffffffu, idx,  2 + half);
        int r2 = __shfl_sync(0xffffffffu, idx,  4 + half);
        int r3 = __shfl_sync(0xffffffffu, idx,  6 + half);
        int r4 = __shfl_sync(0xffffffffu, idx,  8 + half);
        int r5 = __shfl_sync(0xffffffffu, idx, 10 + half);
        int r6 = __shfl_sync(0xffffffffu, idx, 12 + half);
        int r7 = __shfl_sync(0xffffffffu, idx, 14 + half);
        // 8 independent LDG.32 in flight, covering 16 edges
        float2 v0 = __half22float2(__ldg(&h1p[r0 * 16 + fl]));
        float2 v1 = __half22float2(__ldg(&h1p[r1 * 16 + fl]));
        float2 v2 = __half22float2(__ldg(&h1p[r2 * 16 + fl]));
        float2 v3 = __half22float2(__ldg(&h1p[r3 * 16 + fl]));
        float2 v4 = __half22float2(__ldg(&h1p[r4 * 16 + fl]));
        float2 v5 = __half22float2(__ldg(&h1p[r5 * 16 + fl]));
        float2 v6 = __half22float2(__ldg(&h1p[r6 * 16 + fl]));
        float2 v7 = __half22float2(__ldg(&h1p[r7 * 16 + fl]));
        a0.x += v0.x + v4.x; a0.y += v0.y + v4.y;
        a1.x += v1.x + v5.x; a1.y += v1.y + v5.y;
        a2.x += v2.x + v6.x; a2.y += v2.y + v6.y;
        a3.x += v3.x + v7.x; a3.y += v3.y + v7.y;
    }

    float2 accp;
    accp.x = (a0.x + a1.x) + (a2.x + a3.x);
    accp.y = (a0.y + a1.y) + (a2.y + a3.y);
    // merge even/odd halves
    accp.x += __shfl_xor_sync(0xffffffffu, accp.x, 16);
    accp.y += __shfl_xor_sync(0xffffffffu, accp.y, 16);
    // redistribute to per-lane feature layout: lane k holds feature k
    float xe = __shfl_sync(0xffffffffu, accp.x, lane >> 1);
    float xo = __shfl_sync(0xffffffffu, accp.y, lane >> 1);
    float x = (lane & 1) ? xo : xe;

    // tail (< 16 edges), per-feature layout
    for (; j < deg; j++) {
        int s = (int)g_sorted[start + j].x;   // uniform broadcast
        x += __half2float(__ldg(&g_h1h[s * 32 + lane]));
    }
    x /= fmaxf((float)deg, 1.0f);

    float y = sb2a[lane];
#pragma unroll
    for (int k = 0; k < 32; k++) {
        float xk = __shfl_sync(0xffffffffu, x, k);
        y = fmaf(xk, sW2a[k * 32 + lane], y);
    }
    y = fmaxf(y, 0.0f);

    float z = sb2b[lane];
#pragma unroll
    for (int k = 0; k < 32; k++) {
        float yk = __shfl_sync(0xffffffffu, y, k);
        z = fmaf(yk, sW2b[k * 32 + lane], z);
    }
    z = fmaxf(z, 0.0f);  // >= 0 -> int-compare atomicMax is order-safe

    int g = graph_ids[n];
    atomicMax((int*)&g_pooled[g * 32 + lane], __float_as_int(z));
}

// ---------------- classifier head ----------------
__global__ void head_kernel(const float* __restrict__ Wm1, const float* __restrict__ bm1,
                            const float* __restrict__ Wm2, const float* __restrict__ bm2,
                            float* __restrict__ out) {
    int g = threadIdx.x;
    if (g >= NG) return;
    float p[32];
#pragma unroll
    for (int k = 0; k < 32; k++) p[k] = g_pooled[g * 32 + k];
    float hid[16];
#pragma unroll
    for (int jj = 0; jj < 16; jj++) {
        float a = bm1[jj];
#pragma unroll
        for (int k = 0; k < 32; k++) a = fmaf(p[k], Wm1[k * 16 + jj], a);
        hid[jj] = fmaxf(a, 0.0f);
    }
    float l0 = bm2[0], l1 = bm2[1];
#pragma unroll
    for (int jj = 0; jj < 16; jj++) {
        l0 = fmaf(hid[jj], Wm2[jj * 2 + 0], l0);
        l1 = fmaf(hid[jj], Wm2[jj * 2 + 1], l1);
    }
    float m = fmaxf(l0, l1);
    float e0 = expf(l0 - m);
    float e1 = expf(l1 - m);
    float inv = 1.0f / (e0 + e1);
    out[g * 2 + 0] = e0 * inv;
    out[g * 2 + 1] = e1 * inv;
}

extern "C" void kernel_launch(void* const* d_in, const int* in_sizes, int n_in,
                              void* d_out, int out_size) {
    const float* node_feat = (const float*)d_in[0];
    const float* edge_feat = (const float*)d_in[1];
    const int*   src       = (const int*)d_in[2];
    const int*   dst       = (const int*)d_in[3];
    const int*   graph_ids = (const int*)d_in[4];
    const float* W1a = (const float*)d_in[5];
    const float* b1a = (const float*)d_in[6];
    const float* W1b = (const float*)d_in[7];
    const float* b1b = (const float*)d_in[8];
    const float* W2a = (const float*)d_in[9];
    const float* b2a = (const float*)d_in[10];
    const float* W2b = (const float*)d_in[11];
    const float* b2b = (const float*)d_in[12];
    const float* Wm1 = (const float*)d_in[13];
    const float* bm1 = (const float*)d_in[14];
    const float* Wm2 = (const float*)d_in[15];
    const float* bm2 = (const float*)d_in[16];
    float* out = (float*)d_out;

    setup_kernel<<<(NN * 8 + 255) / 256, 256>>>(node_feat);
    sort_kernel<<<NB_SCAN, 256>>>((const int4*)src, (const int4*)dst,
                                  (const float4*)edge_feat);
    node1_kernel<<<NN / 8, 256>>>(W1a, b1a, W1b, b1b);
    node2_kernel<<<NN / 8, 256>>>(W2a, b2a, W2b, b2b, graph_ids);
    head_kernel<<<1, 64>>>(Wm1, bm1, Wm2, bm2, out);
}